// round 1
// baseline (speedup 1.0000x reference)
#include <cuda_runtime.h>
#include <cuda_bf16.h>
#include <math.h>

#define Bsz 64
#define Lsz 512
#define DIN 1024
#define Hsz 1024
#define Gsz 4096
#define ML (Bsz*Lsz)            // 32768
#define OUTN ((size_t)Bsz*Lsz*Hsz) // 33554432

// ---------------- scratch (static device allocations) ----------------
__device__ float g_xproj[(size_t)ML*Gsz];                 // 512 MB
__device__ __nv_bfloat16 g_xhi[(size_t)ML*DIN];
__device__ __nv_bfloat16 g_xlo[(size_t)ML*DIN];
__device__ __nv_bfloat16 g_wxhi[(size_t)Gsz*DIN];
__device__ __nv_bfloat16 g_wxlo[(size_t)Gsz*DIN];
__device__ __nv_bfloat16 g_whhi[(size_t)Gsz*Hsz];
__device__ __nv_bfloat16 g_whlo[(size_t)Gsz*Hsz];
__device__ __nv_bfloat16 g_hhi[2][Bsz*Hsz];
__device__ __nv_bfloat16 g_hlo[2][Bsz*Hsz];
__device__ unsigned g_bar;

// ---------------- helpers ----------------
__device__ __forceinline__ void mma16816(float* c, const unsigned* a, const unsigned* b) {
    asm volatile(
        "mma.sync.aligned.m16n8k16.row.col.f32.bf16.bf16.f32 "
        "{%0,%1,%2,%3}, {%4,%5,%6,%7}, {%8,%9}, {%0,%1,%2,%3};\n"
        : "+f"(c[0]), "+f"(c[1]), "+f"(c[2]), "+f"(c[3])
        : "r"(a[0]), "r"(a[1]), "r"(a[2]), "r"(a[3]), "r"(b[0]), "r"(b[1]));
}

__device__ __forceinline__ float sigmoidf_(float x) {
    return 1.0f / (1.0f + __expf(-x));
}

// ---------------- split kernels ----------------
__global__ void split_x_kernel(const float* __restrict__ x) {
    size_t stride = (size_t)gridDim.x * blockDim.x;
    for (size_t i = (size_t)blockIdx.x * blockDim.x + threadIdx.x;
         i < (size_t)ML * DIN; i += stride) {
        float v = x[i];
        __nv_bfloat16 hi = __float2bfloat16(v);
        g_xhi[i] = hi;
        g_xlo[i] = __float2bfloat16(v - __bfloat162float(hi));
    }
}

__global__ void split_w_kernel(const float* __restrict__ W) {
    size_t stride = (size_t)gridDim.x * blockDim.x;
    for (size_t i = (size_t)blockIdx.x * blockDim.x + threadIdx.x;
         i < (size_t)Gsz * (Hsz + DIN); i += stride) {
        int r = (int)(i >> 11);          // row (0..4095)
        int c = (int)(i & 2047);         // col (0..2047)
        float v = W[i];
        __nv_bfloat16 hi = __float2bfloat16(v);
        __nv_bfloat16 lo = __float2bfloat16(v - __bfloat162float(hi));
        size_t d = (size_t)r * 1024 + (c & 1023);
        if (c < 1024) { g_whhi[d] = hi; g_whlo[d] = lo; }
        else          { g_wxhi[d] = hi; g_wxlo[d] = lo; }
    }
}

__global__ void init_kernel() {
    int i = blockIdx.x * blockDim.x + threadIdx.x;
    if (i == 0) g_bar = 0;
    if (i < Bsz * Hsz) {
        __nv_bfloat16 z = __float2bfloat16(0.0f);
        g_hhi[0][i] = z;
        g_hlo[0][i] = z;
    }
}

// ---------------- phase 1: x_proj GEMM (split bf16, 3 mma) ----------------
#define P1_BM 128
#define P1_BN 128
#define P1_BK 32
#define P1_PAD 8   // row length 40 bf16 -> 80B -> conflict-free

__global__ __launch_bounds__(256) void xproj_kernel(const float* __restrict__ bias) {
    __shared__ __nv_bfloat16 As[2][P1_BM][P1_BK + P1_PAD];
    __shared__ __nv_bfloat16 Bs[2][P1_BN][P1_BK + P1_PAD];

    const int tid = threadIdx.x;
    const int wid = tid >> 5, lane = tid & 31;
    const int g = lane >> 2, tg = lane & 3;
    const int wm = wid & 3;     // rows wm*32 (2 m-tiles of 16)
    const int wn = wid >> 2;    // cols wn*64 (8 n-tiles of 8)
    const int m0 = blockIdx.y * P1_BM;
    const int n0 = blockIdx.x * P1_BN;

    float acc[2][8][4];
    #pragma unroll
    for (int i = 0; i < 2; ++i)
        #pragma unroll
        for (int j = 0; j < 8; ++j)
            #pragma unroll
            for (int k = 0; k < 4; ++k) acc[i][j][k] = 0.0f;

    const int lrow = tid >> 1;            // 0..127
    const int lcb  = (tid & 1) * 16;      // 0 or 16

    for (int k0 = 0; k0 < DIN; k0 += P1_BK) {
        __syncthreads();
        {
            const uint4* s;
            s = (const uint4*)(g_xhi + (size_t)(m0 + lrow) * DIN + k0 + lcb);
            *(uint4*)&As[0][lrow][lcb]     = s[0];
            *(uint4*)&As[0][lrow][lcb + 8] = s[1];
            s = (const uint4*)(g_xlo + (size_t)(m0 + lrow) * DIN + k0 + lcb);
            *(uint4*)&As[1][lrow][lcb]     = s[0];
            *(uint4*)&As[1][lrow][lcb + 8] = s[1];
            s = (const uint4*)(g_wxhi + (size_t)(n0 + lrow) * DIN + k0 + lcb);
            *(uint4*)&Bs[0][lrow][lcb]     = s[0];
            *(uint4*)&Bs[0][lrow][lcb + 8] = s[1];
            s = (const uint4*)(g_wxlo + (size_t)(n0 + lrow) * DIN + k0 + lcb);
            *(uint4*)&Bs[1][lrow][lcb]     = s[0];
            *(uint4*)&Bs[1][lrow][lcb + 8] = s[1];
        }
        __syncthreads();

        #pragma unroll
        for (int kk = 0; kk < 2; ++kk) {
            const int kb = kk * 16;
            unsigned ahi[2][4], alo[2][4];
            #pragma unroll
            for (int mt = 0; mt < 2; ++mt) {
                const int r = wm * 32 + mt * 16 + g;
                ahi[mt][0] = *(const unsigned*)&As[0][r][kb + 2 * tg];
                ahi[mt][1] = *(const unsigned*)&As[0][r + 8][kb + 2 * tg];
                ahi[mt][2] = *(const unsigned*)&As[0][r][kb + 2 * tg + 8];
                ahi[mt][3] = *(const unsigned*)&As[0][r + 8][kb + 2 * tg + 8];
                alo[mt][0] = *(const unsigned*)&As[1][r][kb + 2 * tg];
                alo[mt][1] = *(const unsigned*)&As[1][r + 8][kb + 2 * tg];
                alo[mt][2] = *(const unsigned*)&As[1][r][kb + 2 * tg + 8];
                alo[mt][3] = *(const unsigned*)&As[1][r + 8][kb + 2 * tg + 8];
            }
            #pragma unroll
            for (int nt = 0; nt < 8; ++nt) {
                const int c = wn * 64 + nt * 8 + g;
                unsigned bhi[2], blo[2];
                bhi[0] = *(const unsigned*)&Bs[0][c][kb + 2 * tg];
                bhi[1] = *(const unsigned*)&Bs[0][c][kb + 2 * tg + 8];
                blo[0] = *(const unsigned*)&Bs[1][c][kb + 2 * tg];
                blo[1] = *(const unsigned*)&Bs[1][c][kb + 2 * tg + 8];
                #pragma unroll
                for (int mt = 0; mt < 2; ++mt) {
                    mma16816(acc[mt][nt], ahi[mt], bhi);
                    mma16816(acc[mt][nt], ahi[mt], blo);
                    mma16816(acc[mt][nt], alo[mt], bhi);
                }
            }
        }
    }

    // epilogue: +bias, store fp32
    #pragma unroll
    for (int nt = 0; nt < 8; ++nt) {
        const int c = n0 + wn * 64 + nt * 8 + 2 * tg;
        const float bv0 = bias[c], bv1 = bias[c + 1];
        #pragma unroll
        for (int mt = 0; mt < 2; ++mt) {
            const int r0 = m0 + wm * 32 + mt * 16 + g;
            float2 v0 = make_float2(acc[mt][nt][0] + bv0, acc[mt][nt][1] + bv1);
            float2 v1 = make_float2(acc[mt][nt][2] + bv0, acc[mt][nt][3] + bv1);
            *(float2*)&g_xproj[(size_t)r0 * Gsz + c]       = v0;
            *(float2*)&g_xproj[(size_t)(r0 + 8) * Gsz + c] = v1;
        }
    }
}

// ---------------- phase 2: persistent recurrent LSTM ----------------
// 128 blocks; block owns 8 hidden units (32 gate rows). Wh slice resident in SMEM.
#define NBLK2 128
#define HPERB 8          // hidden units per block
#define NG 32            // gate rows per block (4 * HPERB)
#define WPAD 8           // wh row length 1032
#define KC 128           // k-chunk for h staging
#define HTPAD 8          // htile row length 136

#define SM_WH   (NG * (Hsz + WPAD))            // elems per wh array
#define SM_HT   (Bsz * (KC + HTPAD))           // elems per htile array
#define SMEM_P2 ((size_t)(2*SM_WH + 2*SM_HT) * 2 + (size_t)(Bsz*NG + Bsz*HPERB) * 4)

__global__ __launch_bounds__(256, 1) void lstm_kernel(float* __restrict__ out) {
    extern __shared__ char smem[];
    __nv_bfloat16* whhi = (__nv_bfloat16*)smem;               // [NG][1032]
    __nv_bfloat16* whlo = whhi + SM_WH;
    __nv_bfloat16* hthi = whlo + SM_WH;                        // [64][136]
    __nv_bfloat16* htlo = hthi + SM_HT;
    float* gates = (float*)(htlo + SM_HT);                     // [64][32]
    float* csm   = gates + Bsz * NG;                           // [64][8]

    const int tid = threadIdx.x;
    const int wid = tid >> 5, lane = tid & 31;
    const int g = lane >> 2, tg = lane & 3;
    const int wm = wid & 3;      // rows wm*16
    const int wn = wid >> 2;     // cols wn*16 (2 n-tiles of 8)
    const int j0 = blockIdx.x * HPERB;

    // load Wh slice into SMEM (rows: q*1024 + j0 + jj -> local n = q*8+jj)
    for (int i = tid; i < NG * (Hsz / 8); i += 256) {   // uint4 units: 128 per row
        const int n = i >> 7;
        const int cu = i & 127;
        const int q = n >> 3, jj = n & 7;
        const size_t src = (size_t)(q * 1024 + j0 + jj) * Hsz + cu * 8;
        *(uint4*)&whhi[n * (Hsz + WPAD) + cu * 8] = *(const uint4*)(g_whhi + src);
        *(uint4*)&whlo[n * (Hsz + WPAD) + cu * 8] = *(const uint4*)(g_whlo + src);
    }
    // init c = 0
    for (int i = tid; i < Bsz * HPERB; i += 256) csm[i] = 0.0f;
    __syncthreads();

    volatile unsigned* vb = &g_bar;

    for (int t = 0; t < Lsz; ++t) {
        const int hbuf = t & 1;
        float acc[2][4];
        #pragma unroll
        for (int i = 0; i < 2; ++i)
            #pragma unroll
            for (int k = 0; k < 4; ++k) acc[i][k] = 0.0f;

        for (int kc = 0; kc < Hsz / KC; ++kc) {
            // stage h chunk (hi+lo): 64 x 128 bf16 each
            __syncthreads();
            for (int i = tid; i < Bsz * (KC / 8); i += 256) {  // 1024 uint4
                const int row = i >> 4;
                const int cu = i & 15;
                const size_t src = (size_t)row * Hsz + kc * KC + cu * 8;
                *(uint4*)&hthi[row * (KC + HTPAD) + cu * 8] = *(const uint4*)(&g_hhi[hbuf][0] + src);
                *(uint4*)&htlo[row * (KC + HTPAD) + cu * 8] = *(const uint4*)(&g_hlo[hbuf][0] + src);
            }
            __syncthreads();

            #pragma unroll
            for (int ks = 0; ks < KC / 16; ++ks) {
                const int kb = ks * 16;
                unsigned ahi[4], alo[4];
                const int r = wm * 16 + g;
                ahi[0] = *(const unsigned*)&hthi[r * (KC + HTPAD) + kb + 2 * tg];
                ahi[1] = *(const unsigned*)&hthi[(r + 8) * (KC + HTPAD) + kb + 2 * tg];
                ahi[2] = *(const unsigned*)&hthi[r * (KC + HTPAD) + kb + 2 * tg + 8];
                ahi[3] = *(const unsigned*)&hthi[(r + 8) * (KC + HTPAD) + kb + 2 * tg + 8];
                alo[0] = *(const unsigned*)&htlo[r * (KC + HTPAD) + kb + 2 * tg];
                alo[1] = *(const unsigned*)&htlo[(r + 8) * (KC + HTPAD) + kb + 2 * tg];
                alo[2] = *(const unsigned*)&htlo[r * (KC + HTPAD) + kb + 2 * tg + 8];
                alo[3] = *(const unsigned*)&htlo[(r + 8) * (KC + HTPAD) + kb + 2 * tg + 8];
                const int koff = kc * KC + kb + 2 * tg;
                #pragma unroll
                for (int nt = 0; nt < 2; ++nt) {
                    const int c = wn * 16 + nt * 8 + g;
                    unsigned bhi[2], blo[2];
                    bhi[0] = *(const unsigned*)&whhi[c * (Hsz + WPAD) + koff];
                    bhi[1] = *(const unsigned*)&whhi[c * (Hsz + WPAD) + koff + 8];
                    blo[0] = *(const unsigned*)&whlo[c * (Hsz + WPAD) + koff];
                    blo[1] = *(const unsigned*)&whlo[c * (Hsz + WPAD) + koff + 8];
                    mma16816(acc[nt], ahi, bhi);
                    mma16816(acc[nt], ahi, blo);
                    mma16816(acc[nt], alo, bhi);
                }
            }
        }

        // stage gate pre-activations (recurrent part) to SMEM
        __syncthreads();
        #pragma unroll
        for (int nt = 0; nt < 2; ++nt) {
            const int c = wn * 16 + nt * 8 + 2 * tg;
            const int r = wm * 16 + g;
            gates[r * NG + c]           = acc[nt][0];
            gates[r * NG + c + 1]       = acc[nt][1];
            gates[(r + 8) * NG + c]     = acc[nt][2];
            gates[(r + 8) * NG + c + 1] = acc[nt][3];
        }
        __syncthreads();

        // LSTM cell: 512 items (b, jj)
        const int nb = (t + 1) & 1;
        for (int it = tid; it < Bsz * HPERB; it += 256) {
            const int b = it >> 3, jj = it & 7;
            const int j = j0 + jj;
            const size_t xpb = ((size_t)b * Lsz + t) * Gsz + j;
            const float pf = gates[b * NG + 0 * 8 + jj] + g_xproj[xpb];
            const float pi = gates[b * NG + 1 * 8 + jj] + g_xproj[xpb + 1024];
            const float pg = gates[b * NG + 2 * 8 + jj] + g_xproj[xpb + 2048];
            const float po = gates[b * NG + 3 * 8 + jj] + g_xproj[xpb + 3072];
            const float f = sigmoidf_(pf);
            const float ii = sigmoidf_(pi);
            const float gg = tanhf(pg);
            const float o = sigmoidf_(po);
            const float c_new = f * csm[it] + ii * gg;
            csm[it] = c_new;
            const float h = o * tanhf(c_new);
            out[((size_t)b * Lsz + t) * Hsz + j] = h;
            const __nv_bfloat16 hh = __float2bfloat16(h);
            g_hhi[nb][b * Hsz + j] = hh;
            g_hlo[nb][b * Hsz + j] = __float2bfloat16(h - __bfloat162float(hh));
        }

        // grid barrier (release h writes, wait for all blocks)
        __threadfence();
        __syncthreads();
        if (tid == 0) {
            atomicAdd(&g_bar, 1u);
            const unsigned target = (unsigned)(t + 1) * gridDim.x;
            while (*vb < target) { }
            __threadfence();
        }
        __syncthreads();
    }

    // finals: h_fin from outputs (our own fp32 writes), c_fin from SMEM
    for (int it = tid; it < Bsz * HPERB; it += 256) {
        const int b = it >> 3, jj = it & 7;
        const int j = j0 + jj;
        const float hv = out[((size_t)b * Lsz + (Lsz - 1)) * Hsz + j];
        out[OUTN + (size_t)b * Hsz + j] = hv;
        out[OUTN + (size_t)Bsz * Hsz + (size_t)b * Hsz + j] = csm[it];
    }
}

// ---------------- launcher ----------------
extern "C" void kernel_launch(void* const* d_in, const int* in_sizes, int n_in,
                              void* d_out, int out_size) {
    const float* x = (const float*)d_in[0];
    const float* W = (const float*)d_in[1];
    const float* b = (const float*)d_in[2];
    float* out = (float*)d_out;

    split_x_kernel<<<2048, 256>>>(x);
    split_w_kernel<<<1024, 256>>>(W);
    init_kernel<<<256, 256>>>();

    dim3 g1(Gsz / P1_BN, ML / P1_BM);   // (32, 256)
    xproj_kernel<<<g1, 256>>>(b);

    cudaFuncSetAttribute(lstm_kernel, cudaFuncAttributeMaxDynamicSharedMemorySize,
                         (int)SMEM_P2);
    lstm_kernel<<<NBLK2, 256, SMEM_P2>>>(out);
}

// round 2
// speedup vs baseline: 1.5494x; 1.5494x over previous
#include <cuda_runtime.h>
#include <cuda_bf16.h>
#include <math.h>

#define Bsz 64
#define Lsz 512
#define DIN 1024
#define Hsz 1024
#define Gsz 4096
#define ML (Bsz*Lsz)            // 32768
#define OUTN ((size_t)Bsz*Lsz*Hsz) // 33554432

// ---------------- scratch (static device allocations) ----------------
__device__ float g_xproj[(size_t)ML*Gsz];                 // 512 MB
__device__ __nv_bfloat16 g_xhi[(size_t)ML*DIN];
__device__ __nv_bfloat16 g_xlo[(size_t)ML*DIN];
__device__ __nv_bfloat16 g_wxhi[(size_t)Gsz*DIN];
__device__ __nv_bfloat16 g_wxlo[(size_t)Gsz*DIN];
__device__ __nv_bfloat16 g_whhi[(size_t)Gsz*Hsz];
__device__ __nv_bfloat16 g_whlo[(size_t)Gsz*Hsz];
__device__ __nv_bfloat16 g_hhi[2][Bsz*Hsz];
__device__ __nv_bfloat16 g_hlo[2][Bsz*Hsz];
__device__ unsigned g_bar;

// ---------------- helpers ----------------
__device__ __forceinline__ void mma16816(float* c, const unsigned* a, const unsigned* b) {
    asm volatile(
        "mma.sync.aligned.m16n8k16.row.col.f32.bf16.bf16.f32 "
        "{%0,%1,%2,%3}, {%4,%5,%6,%7}, {%8,%9}, {%0,%1,%2,%3};\n"
        : "+f"(c[0]), "+f"(c[1]), "+f"(c[2]), "+f"(c[3])
        : "r"(a[0]), "r"(a[1]), "r"(a[2]), "r"(a[3]), "r"(b[0]), "r"(b[1]));
}

__device__ __forceinline__ void cp16(void* dst, const void* src) {
    unsigned d = (unsigned)__cvta_generic_to_shared(dst);
    asm volatile("cp.async.cg.shared.global [%0], [%1], 16;\n" :: "r"(d), "l"(src));
}
__device__ __forceinline__ void cp_commit() {
    asm volatile("cp.async.commit_group;\n");
}
__device__ __forceinline__ void cp_wait1() {
    asm volatile("cp.async.wait_group 1;\n");
}
__device__ __forceinline__ void cp_wait0() {
    asm volatile("cp.async.wait_group 0;\n");
}

__device__ __forceinline__ float sigmoidf_(float x) {
    return 1.0f / (1.0f + __expf(-x));
}

// ---------------- split kernels ----------------
__global__ void split_x_kernel(const float* __restrict__ x) {
    size_t stride = (size_t)gridDim.x * blockDim.x;
    for (size_t i = (size_t)blockIdx.x * blockDim.x + threadIdx.x;
         i < (size_t)ML * DIN; i += stride) {
        float v = x[i];
        __nv_bfloat16 hi = __float2bfloat16(v);
        g_xhi[i] = hi;
        g_xlo[i] = __float2bfloat16(v - __bfloat162float(hi));
    }
}

__global__ void split_w_kernel(const float* __restrict__ W) {
    size_t stride = (size_t)gridDim.x * blockDim.x;
    for (size_t i = (size_t)blockIdx.x * blockDim.x + threadIdx.x;
         i < (size_t)Gsz * (Hsz + DIN); i += stride) {
        int r = (int)(i >> 11);          // row (0..4095)
        int c = (int)(i & 2047);         // col (0..2047)
        float v = W[i];
        __nv_bfloat16 hi = __float2bfloat16(v);
        __nv_bfloat16 lo = __float2bfloat16(v - __bfloat162float(hi));
        size_t d = (size_t)r * 1024 + (c & 1023);
        if (c < 1024) { g_whhi[d] = hi; g_whlo[d] = lo; }
        else          { g_wxhi[d] = hi; g_wxlo[d] = lo; }
    }
}

__global__ void init_kernel() {
    int i = blockIdx.x * blockDim.x + threadIdx.x;
    if (i == 0) g_bar = 0;
    if (i < Bsz * Hsz) {
        __nv_bfloat16 z = __float2bfloat16(0.0f);
        g_hhi[0][i] = z;
        g_hlo[0][i] = z;
    }
}

// ---------------- phase 1: x_proj GEMM (split bf16, 3 mma, cp.async 2-stage) ----------------
#define P1_BM 128
#define P1_BN 128
#define P1_BK 32
#define P1_PAD 8   // row length 40 bf16 -> 80B rows, 16B aligned

__global__ __launch_bounds__(256) void xproj_kernel(const float* __restrict__ bias) {
    __shared__ __nv_bfloat16 As[2][2][P1_BM][P1_BK + P1_PAD];  // [buf][hi/lo]
    __shared__ __nv_bfloat16 Bs[2][2][P1_BN][P1_BK + P1_PAD];

    const int tid = threadIdx.x;
    const int wid = tid >> 5, lane = tid & 31;
    const int g = lane >> 2, tg = lane & 3;
    const int wm = wid & 3;     // rows wm*32 (2 m-tiles of 16)
    const int wn = wid >> 2;    // cols wn*64 (8 n-tiles of 8)
    const int m0 = blockIdx.y * P1_BM;
    const int n0 = blockIdx.x * P1_BN;

    float acc[2][8][4];
    #pragma unroll
    for (int i = 0; i < 2; ++i)
        #pragma unroll
        for (int j = 0; j < 8; ++j)
            #pragma unroll
            for (int k = 0; k < 4; ++k) acc[i][j][k] = 0.0f;

    const int lrow = tid >> 1;            // 0..127
    const int lcb  = (tid & 1) * 16;      // 0 or 16

    const __nv_bfloat16* srcAh = g_xhi  + (size_t)(m0 + lrow) * DIN + lcb;
    const __nv_bfloat16* srcAl = g_xlo  + (size_t)(m0 + lrow) * DIN + lcb;
    const __nv_bfloat16* srcBh = g_wxhi + (size_t)(n0 + lrow) * DIN + lcb;
    const __nv_bfloat16* srcBl = g_wxlo + (size_t)(n0 + lrow) * DIN + lcb;

    auto stage = [&](int buf, int k0) {
        cp16(&As[buf][0][lrow][lcb],     srcAh + k0);
        cp16(&As[buf][0][lrow][lcb + 8], srcAh + k0 + 8);
        cp16(&As[buf][1][lrow][lcb],     srcAl + k0);
        cp16(&As[buf][1][lrow][lcb + 8], srcAl + k0 + 8);
        cp16(&Bs[buf][0][lrow][lcb],     srcBh + k0);
        cp16(&Bs[buf][0][lrow][lcb + 8], srcBh + k0 + 8);
        cp16(&Bs[buf][1][lrow][lcb],     srcBl + k0);
        cp16(&Bs[buf][1][lrow][lcb + 8], srcBl + k0 + 8);
        cp_commit();
    };

    stage(0, 0);

    for (int k0 = 0; k0 < DIN; k0 += P1_BK) {
        const int buf = (k0 >> 5) & 1;
        const bool more = (k0 + P1_BK) < DIN;
        if (more) stage(buf ^ 1, k0 + P1_BK);
        if (more) cp_wait1(); else cp_wait0();
        __syncthreads();

        #pragma unroll
        for (int kk = 0; kk < 2; ++kk) {
            const int kb = kk * 16;
            unsigned ahi[2][4], alo[2][4];
            #pragma unroll
            for (int mt = 0; mt < 2; ++mt) {
                const int r = wm * 32 + mt * 16 + g;
                ahi[mt][0] = *(const unsigned*)&As[buf][0][r][kb + 2 * tg];
                ahi[mt][1] = *(const unsigned*)&As[buf][0][r + 8][kb + 2 * tg];
                ahi[mt][2] = *(const unsigned*)&As[buf][0][r][kb + 2 * tg + 8];
                ahi[mt][3] = *(const unsigned*)&As[buf][0][r + 8][kb + 2 * tg + 8];
                alo[mt][0] = *(const unsigned*)&As[buf][1][r][kb + 2 * tg];
                alo[mt][1] = *(const unsigned*)&As[buf][1][r + 8][kb + 2 * tg];
                alo[mt][2] = *(const unsigned*)&As[buf][1][r][kb + 2 * tg + 8];
                alo[mt][3] = *(const unsigned*)&As[buf][1][r + 8][kb + 2 * tg + 8];
            }
            #pragma unroll
            for (int nt = 0; nt < 8; ++nt) {
                const int c = wn * 64 + nt * 8 + g;
                unsigned bhi[2], blo[2];
                bhi[0] = *(const unsigned*)&Bs[buf][0][c][kb + 2 * tg];
                bhi[1] = *(const unsigned*)&Bs[buf][0][c][kb + 2 * tg + 8];
                blo[0] = *(const unsigned*)&Bs[buf][1][c][kb + 2 * tg];
                blo[1] = *(const unsigned*)&Bs[buf][1][c][kb + 2 * tg + 8];
                #pragma unroll
                for (int mt = 0; mt < 2; ++mt) {
                    mma16816(acc[mt][nt], ahi[mt], bhi);
                    mma16816(acc[mt][nt], ahi[mt], blo);
                    mma16816(acc[mt][nt], alo[mt], bhi);
                }
            }
        }
        __syncthreads();
    }

    // epilogue: +bias, store fp32
    #pragma unroll
    for (int nt = 0; nt < 8; ++nt) {
        const int c = n0 + wn * 64 + nt * 8 + 2 * tg;
        const float bv0 = bias[c], bv1 = bias[c + 1];
        #pragma unroll
        for (int mt = 0; mt < 2; ++mt) {
            const int r0 = m0 + wm * 32 + mt * 16 + g;
            float2 v0 = make_float2(acc[mt][nt][0] + bv0, acc[mt][nt][1] + bv1);
            float2 v1 = make_float2(acc[mt][nt][2] + bv0, acc[mt][nt][3] + bv1);
            *(float2*)&g_xproj[(size_t)r0 * Gsz + c]       = v0;
            *(float2*)&g_xproj[(size_t)(r0 + 8) * Gsz + c] = v1;
        }
    }
}

// ---------------- phase 2: persistent recurrent LSTM ----------------
// 128 blocks; block owns 8 hidden units (32 gate rows). Wh slice resident in SMEM.
// h chunks double-buffered via cp.async; xproj prefetched under barrier spin.
#define NBLK2 128
#define HPERB 8          // hidden units per block
#define NG 32            // gate rows per block (4 * HPERB)
#define WPAD 8           // wh row length 1032
#define KC 128           // k-chunk for h staging
#define HTPAD 8          // htile row length 136
#define NCHUNK (Hsz / KC)

#define SM_WH   (NG * (Hsz + WPAD))            // elems per wh array
#define SM_HT   (Bsz * (KC + HTPAD))           // elems per htile array
#define SMEM_P2 ((size_t)(2*SM_WH + 4*SM_HT) * 2 + (size_t)(Bsz*NG + Bsz*HPERB) * 4)

__global__ __launch_bounds__(256, 1) void lstm_kernel(float* __restrict__ out) {
    extern __shared__ char smem[];
    __nv_bfloat16* whhi = (__nv_bfloat16*)smem;               // [NG][1032]
    __nv_bfloat16* whlo = whhi + SM_WH;
    __nv_bfloat16* hthi[2];
    __nv_bfloat16* htlo[2];
    hthi[0] = whlo + SM_WH;                                    // [64][136]
    htlo[0] = hthi[0] + SM_HT;
    hthi[1] = htlo[0] + SM_HT;
    htlo[1] = hthi[1] + SM_HT;
    float* gates = (float*)(htlo[1] + SM_HT);                  // [64][32]
    float* csm   = gates + Bsz * NG;                           // [64][8]

    const int tid = threadIdx.x;
    const int wid = tid >> 5, lane = tid & 31;
    const int g = lane >> 2, tg = lane & 3;
    const int wm = wid & 3;      // rows wm*16
    const int wn = wid >> 2;     // cols wn*16 (2 n-tiles of 8)
    const int j0 = blockIdx.x * HPERB;

    // load Wh slice into SMEM (rows: q*1024 + j0 + jj -> local n = q*8+jj)
    for (int i = tid; i < NG * (Hsz / 8); i += 256) {   // uint4 units: 128 per row
        const int n = i >> 7;
        const int cu = i & 127;
        const int q = n >> 3, jj = n & 7;
        const size_t src = (size_t)(q * 1024 + j0 + jj) * Hsz + cu * 8;
        *(uint4*)&whhi[n * (Hsz + WPAD) + cu * 8] = *(const uint4*)(g_whhi + src);
        *(uint4*)&whlo[n * (Hsz + WPAD) + cu * 8] = *(const uint4*)(g_whlo + src);
    }
    // init c = 0
    for (int i = tid; i < Bsz * HPERB; i += 256) csm[i] = 0.0f;
    __syncthreads();

    volatile unsigned* vb = &g_bar;

    // cell-update item mapping: this thread handles it0=tid, it1=tid+256
    const int b_0 = tid >> 3, jj_0 = tid & 7;
    const int b_1 = (tid + 256) >> 3, jj_1 = (tid + 256) & 7;

    // prefetch xproj for step 0
    float xp[8];
    {
        const size_t base0 = ((size_t)b_0 * Lsz + 0) * Gsz + j0 + jj_0;
        const size_t base1 = ((size_t)b_1 * Lsz + 0) * Gsz + j0 + jj_1;
        xp[0] = __ldg(g_xproj + base0);
        xp[1] = __ldg(g_xproj + base0 + 1024);
        xp[2] = __ldg(g_xproj + base0 + 2048);
        xp[3] = __ldg(g_xproj + base0 + 3072);
        xp[4] = __ldg(g_xproj + base1);
        xp[5] = __ldg(g_xproj + base1 + 1024);
        xp[6] = __ldg(g_xproj + base1 + 2048);
        xp[7] = __ldg(g_xproj + base1 + 3072);
    }

    // h-chunk staging lambda (cp.async): 8 cp16 per thread
    auto stage_h = [&](int buf, int kc, int hbuf) {
        const __nv_bfloat16* shi = &g_hhi[hbuf][0];
        const __nv_bfloat16* slo = &g_hlo[hbuf][0];
        #pragma unroll
        for (int q = 0; q < 4; ++q) {
            const int i = tid + q * 256;            // 0..1023
            const int row = i >> 4;
            const int cu = i & 15;
            const size_t src = (size_t)row * Hsz + kc * KC + cu * 8;
            cp16(&hthi[buf][row * (KC + HTPAD) + cu * 8], shi + src);
            cp16(&htlo[buf][row * (KC + HTPAD) + cu * 8], slo + src);
        }
        cp_commit();
    };

    for (int t = 0; t < Lsz; ++t) {
        const int hbuf = t & 1;
        float acc[2][4];
        #pragma unroll
        for (int i = 0; i < 2; ++i)
            #pragma unroll
            for (int k = 0; k < 4; ++k) acc[i][k] = 0.0f;

        stage_h(0, 0, hbuf);

        for (int kc = 0; kc < NCHUNK; ++kc) {
            const int buf = kc & 1;
            const bool more = (kc + 1) < NCHUNK;
            if (more) stage_h(buf ^ 1, kc + 1, hbuf);
            if (more) cp_wait1(); else cp_wait0();
            __syncthreads();

            const __nv_bfloat16* thi = hthi[buf];
            const __nv_bfloat16* tlo = htlo[buf];

            #pragma unroll
            for (int ks = 0; ks < KC / 16; ++ks) {
                const int kb = ks * 16;
                unsigned ahi[4], alo[4];
                const int r = wm * 16 + g;
                ahi[0] = *(const unsigned*)&thi[r * (KC + HTPAD) + kb + 2 * tg];
                ahi[1] = *(const unsigned*)&thi[(r + 8) * (KC + HTPAD) + kb + 2 * tg];
                ahi[2] = *(const unsigned*)&thi[r * (KC + HTPAD) + kb + 2 * tg + 8];
                ahi[3] = *(const unsigned*)&thi[(r + 8) * (KC + HTPAD) + kb + 2 * tg + 8];
                alo[0] = *(const unsigned*)&tlo[r * (KC + HTPAD) + kb + 2 * tg];
                alo[1] = *(const unsigned*)&tlo[(r + 8) * (KC + HTPAD) + kb + 2 * tg];
                alo[2] = *(const unsigned*)&tlo[r * (KC + HTPAD) + kb + 2 * tg + 8];
                alo[3] = *(const unsigned*)&tlo[(r + 8) * (KC + HTPAD) + kb + 2 * tg + 8];
                const int koff = kc * KC + kb + 2 * tg;
                #pragma unroll
                for (int nt = 0; nt < 2; ++nt) {
                    const int c = wn * 16 + nt * 8 + g;
                    unsigned bhi[2], blo[2];
                    bhi[0] = *(const unsigned*)&whhi[c * (Hsz + WPAD) + koff];
                    bhi[1] = *(const unsigned*)&whhi[c * (Hsz + WPAD) + koff + 8];
                    blo[0] = *(const unsigned*)&whlo[c * (Hsz + WPAD) + koff];
                    blo[1] = *(const unsigned*)&whlo[c * (Hsz + WPAD) + koff + 8];
                    mma16816(acc[nt], ahi, bhi);
                    mma16816(acc[nt], ahi, blo);
                    mma16816(acc[nt], alo, bhi);
                }
            }
            __syncthreads();
        }

        // stage gate pre-activations (recurrent part) to SMEM
        #pragma unroll
        for (int nt = 0; nt < 2; ++nt) {
            const int c = wn * 16 + nt * 8 + 2 * tg;
            const int r = wm * 16 + g;
            gates[r * NG + c]           = acc[nt][0];
            gates[r * NG + c + 1]       = acc[nt][1];
            gates[(r + 8) * NG + c]     = acc[nt][2];
            gates[(r + 8) * NG + c + 1] = acc[nt][3];
        }
        __syncthreads();

        // LSTM cell: 512 items (b, jj); xp already prefetched for this step
        const int nb = (t + 1) & 1;
        {
            // item 0
            {
                const int it = tid;
                const int b = b_0, jj = jj_0, j = j0 + jj;
                const float pf = gates[b * NG + 0 * 8 + jj] + xp[0];
                const float pi = gates[b * NG + 1 * 8 + jj] + xp[1];
                const float pg = gates[b * NG + 2 * 8 + jj] + xp[2];
                const float po = gates[b * NG + 3 * 8 + jj] + xp[3];
                const float f = sigmoidf_(pf);
                const float ii = sigmoidf_(pi);
                const float gg = tanhf(pg);
                const float o = sigmoidf_(po);
                const float c_new = f * csm[it] + ii * gg;
                csm[it] = c_new;
                const float h = o * tanhf(c_new);
                out[((size_t)b * Lsz + t) * Hsz + j] = h;
                const __nv_bfloat16 hh = __float2bfloat16(h);
                g_hhi[nb][b * Hsz + j] = hh;
                g_hlo[nb][b * Hsz + j] = __float2bfloat16(h - __bfloat162float(hh));
            }
            // item 1
            {
                const int it = tid + 256;
                const int b = b_1, jj = jj_1, j = j0 + jj;
                const float pf = gates[b * NG + 0 * 8 + jj] + xp[4];
                const float pi = gates[b * NG + 1 * 8 + jj] + xp[5];
                const float pg = gates[b * NG + 2 * 8 + jj] + xp[6];
                const float po = gates[b * NG + 3 * 8 + jj] + xp[7];
                const float f = sigmoidf_(pf);
                const float ii = sigmoidf_(pi);
                const float gg = tanhf(pg);
                const float o = sigmoidf_(po);
                const float c_new = f * csm[it] + ii * gg;
                csm[it] = c_new;
                const float h = o * tanhf(c_new);
                out[((size_t)b * Lsz + t) * Hsz + j] = h;
                const __nv_bfloat16 hh = __float2bfloat16(h);
                g_hhi[nb][b * Hsz + j] = hh;
                g_hlo[nb][b * Hsz + j] = __float2bfloat16(h - __bfloat162float(hh));
            }
        }

        // grid barrier (arrive, then prefetch next xproj under the spin, then wait)
        __threadfence();
        __syncthreads();
        if (tid == 0) atomicAdd(&g_bar, 1u);
        if (t + 1 < Lsz) {
            const size_t base0 = ((size_t)b_0 * Lsz + (t + 1)) * Gsz + j0 + jj_0;
            const size_t base1 = ((size_t)b_1 * Lsz + (t + 1)) * Gsz + j0 + jj_1;
            xp[0] = __ldg(g_xproj + base0);
            xp[1] = __ldg(g_xproj + base0 + 1024);
            xp[2] = __ldg(g_xproj + base0 + 2048);
            xp[3] = __ldg(g_xproj + base0 + 3072);
            xp[4] = __ldg(g_xproj + base1);
            xp[5] = __ldg(g_xproj + base1 + 1024);
            xp[6] = __ldg(g_xproj + base1 + 2048);
            xp[7] = __ldg(g_xproj + base1 + 3072);
        }
        if (tid == 0) {
            const unsigned target = (unsigned)(t + 1) * gridDim.x;
            while (*vb < target) { }
            __threadfence();
        }
        __syncthreads();
    }

    // finals: h_fin from outputs (our own fp32 writes), c_fin from SMEM
    for (int it = tid; it < Bsz * HPERB; it += 256) {
        const int b = it >> 3, jj = it & 7;
        const int j = j0 + jj;
        const float hv = out[((size_t)b * Lsz + (Lsz - 1)) * Hsz + j];
        out[OUTN + (size_t)b * Hsz + j] = hv;
        out[OUTN + (size_t)Bsz * Hsz + (size_t)b * Hsz + j] = csm[it];
    }
}

// ---------------- launcher ----------------
extern "C" void kernel_launch(void* const* d_in, const int* in_sizes, int n_in,
                              void* d_out, int out_size) {
    const float* x = (const float*)d_in[0];
    const float* W = (const float*)d_in[1];
    const float* b = (const float*)d_in[2];
    float* out = (float*)d_out;

    split_x_kernel<<<2048, 256>>>(x);
    split_w_kernel<<<1024, 256>>>(W);
    init_kernel<<<256, 256>>>();

    dim3 g1(Gsz / P1_BN, ML / P1_BM);   // (32, 256)
    xproj_kernel<<<g1, 256>>>(b);

    cudaFuncSetAttribute(lstm_kernel, cudaFuncAttributeMaxDynamicSharedMemorySize,
                         (int)SMEM_P2);
    lstm_kernel<<<NBLK2, 256, SMEM_P2>>>(out);
}